// round 17
// baseline (speedup 1.0000x reference)
#include <cuda_runtime.h>
#include <math.h>

typedef unsigned long long ull;

// Problem constants
#define B    512
#define IU   8
#define C    1152
#define J    10
#define S    16
#define NR   3
#define R    (B*IU)      // 4096

// Tiling
#define CG   64          // c's per block group
#define NCG  (C/CG)      // 18 c-groups -> 18 partial groups
#define CCB  8           // c's per subchunk
#define NSUB (CG/CCB)    // 8
#define BT   64          // b's per block
#define NBT  (B/BT)      // 8
#define NTHR 512
#define WJS  72          // smem ull stride per (c,j) row (padded from 64)
#define WROW 64          // gmem ull per (c,j) row
#define WSUB (CCB*J*WJS) // 5760 ull
#define XSUBF (CCB*BT*IU) // 4096 floats per x subchunk (UNduplicated)

// Scratch (__device__ globals; no allocation)
__device__ __align__(16) float g_xT[(size_t)C*R];       // plain x [c][b*8+i] 18.9MB
__device__ __align__(16) ull  g_Wp[(size_t)C*J*WROW];   // packed W (s,s+8)   5.9MB
__device__ float g_bA[C*J];                              // b after iter 1
__device__ __align__(16) ull  g_sp2[NCG][(size_t)J*B*8];   // s partials 5.9MB
__device__ __align__(16) ull  g_v2[(size_t)J*B*8];         // packed v
__device__ float g_bp[NBT][C*J];                            // delta_b partials

// SMEM layouts
struct SMemS {
    ull   Wp[2][WSUB];       // 92160 B
    float xf[2][XSUBF];      // 32768 B
    ull   ex[256][4];        // 8192 B  c-half combine buffer
    float ccs[CG*J];         // 2560 B
    float bn[CG*J];          // 2560 B
};
struct SMemB {
    ull   Wp[2][WSUB];       // 92160 B
    float xf[2][XSUBF];      // 32768 B
    float dsm[16][4*J];      // 2560 B  per-warp delta partials (4 cl's each)
};

// ---- packed f32x2 helpers ------------------------------------------------
__device__ __forceinline__ void fma2(ull& d, ull a, ull b) {
    asm("fma.rn.f32x2 %0, %1, %2, %0;" : "+l"(d) : "l"(a), "l"(b));
}
__device__ __forceinline__ ull add2(ull a, ull b) {
    ull d; asm("add.rn.f32x2 %0, %1, %2;" : "=l"(d) : "l"(a), "l"(b)); return d;
}
__device__ __forceinline__ ull pack2(float lo, float hi) {
    return ((ull)__float_as_uint(hi) << 32) | (ull)__float_as_uint(lo);
}
__device__ __forceinline__ ull dup2(float f) {
    unsigned u = __float_as_uint(f); return ((ull)u << 32) | (ull)u;
}
__device__ __forceinline__ float lo2(ull v) { return __uint_as_float((unsigned)v); }
__device__ __forceinline__ float hi2(ull v) { return __uint_as_float((unsigned)(v >> 32)); }

// ---- cp.async helpers ----------------------------------------------------
__device__ __forceinline__ void cpa16(void* dst, const void* src) {
    unsigned s = (unsigned)__cvta_generic_to_shared(dst);
    asm volatile("cp.async.cg.shared.global [%0], [%1], 16;" :: "r"(s), "l"(src));
}
__device__ __forceinline__ void cpcommit() {
    asm volatile("cp.async.commit_group;" ::: "memory");
}
template <int N> __device__ __forceinline__ void cpwait() {
    asm volatile("cp.async.wait_group %0;" :: "n"(N) : "memory");
}

// ---- PDL helpers -----------------------------------------------------------
__device__ __forceinline__ void gdc_launch() {
    asm volatile("griddepcontrol.launch_dependents;");
}
__device__ __forceinline__ void gdc_wait() {
    asm volatile("griddepcontrol.wait;" ::: "memory");
}

// ---------------------------------------------------------------------------
// Prep: x[b][i][c] -> g_xT[c][b*8+i] (plain float)
// ---------------------------------------------------------------------------
__global__ void k_transpose(const float* __restrict__ x) {
    gdc_launch();
    __shared__ float t[32][33];
    int cb = blockIdx.x * 32, rb = blockIdx.y * 32;
    int tx = threadIdx.x, ty = threadIdx.y;
    #pragma unroll
    for (int k = 0; k < 32; k += 8)
        t[ty + k][tx] = x[(size_t)(rb + ty + k) * C + cb + tx];
    __syncthreads();
    #pragma unroll
    for (int k = 0; k < 32; k += 8)
        g_xT[(size_t)(cb + ty + k) * R + rb + tx] = t[tx][ty + k];
}

// Prep: W[c][j][s][i] -> g_Wp[cj][ih*32 + il*8 + sh] = (W[..sh..i], W[..sh+8..i])
__global__ void k_prepW(const float* __restrict__ W) {
    gdc_launch();
    int gid = blockIdx.x * 256 + threadIdx.x;
    if (gid >= C * J * WROW) return;
    int sh = gid & 7, il = (gid >> 3) & 3, ih = (gid >> 5) & 1, cj = gid >> 6;
    int i = ih * 4 + il;
    float lo = W[((size_t)cj * 16 + sh) * 8 + i];
    float hi = W[((size_t)cj * 16 + sh + 8) * 8 + i];
    g_Wp[(size_t)cj * WROW + ih * 32 + il * 8 + sh] = pack2(lo, hi);
}

// ---------------------------------------------------------------------------
// cp.async stagers
// ---------------------------------------------------------------------------
__device__ __forceinline__ void issue_W(ull* Wb, int cstart, int tid) {
    const ull* src = g_Wp + (size_t)cstart * J * WROW;
    #pragma unroll
    for (int t = tid; t < CCB * J * 32; t += NTHR) {
        int row = t >> 5, ch = t & 31;
        cpa16(Wb + row * WJS + ch * 2, src + row * WROW + ch * 2);
    }
}
// x: 4096 floats = 1024 16B-chunks per subchunk
__device__ __forceinline__ void issue_x(float* xb, int cstart, int b0, int tid) {
    #pragma unroll
    for (int t = tid; t < XSUBF / 4; t += NTHR) {
        int cl = t >> 7, ch = t & 127;    // 128 chunks per c
        cpa16(xb + cl * (BT * IU) + ch * 4,
              g_xT + (size_t)(cstart + cl) * R + (size_t)b0 * IU + ch * 4);
    }
}

// ---------------------------------------------------------------------------
// K_s: partial s[j,b,(s,s+8)] over this block's 64 c's.
// Thread = sh(8) x jg(2) x bq(16) x ch(2); ch = c-half handles 4 of the 8
// subchunk cl's; halves combined via SMEM at the end.
// MODE 1: in-block b-update + softmax (from g_bp), rescale staged W by cc.
// MODE 0: first iteration, cc uniform -> 0.1 postscale in k_rs.
// ---------------------------------------------------------------------------
template <int MODE, int EPOCH>
__global__ void __launch_bounds__(NTHR, 1) k_s() {
    extern __shared__ char smraw[];
    SMemS& sm = *(SMemS*)smraw;
    int tid = threadIdx.x;
    int cg = blockIdx.x, bt = blockIdx.y;
    int c0 = cg * CG, b0 = bt * BT;
    int sh = tid & 7;
    int jb = ((tid >> 3) & 1) * 5;
    int bq = (tid >> 4) & 15;
    int ch = tid >> 8;

    gdc_launch();
    if (MODE == 0) gdc_wait();      // staging sources written by prep kernels

    issue_W(sm.Wp[0], c0, tid);
    issue_x(sm.xf[0], c0, b0, tid);
    cpcommit();

    if (MODE == 1) {
        gdc_wait();                 // g_bp written by the preceding k_b
        for (int t = tid; t < CG * J; t += NTHR) {
            int j = t % J, c = c0 + t / J;
            float d = 0.f;
            #pragma unroll
            for (int p = 0; p < NBT; p++) d += g_bp[p][c * J + j];
            float nb = d * (1.f / B);
            if (EPOCH == 1) nb += g_bA[c * J + j];
            sm.bn[t] = nb;
            if (bt == 0 && EPOCH == 0) g_bA[c * J + j] = nb;
        }
        __syncthreads();
        for (int t = tid; t < CG * J; t += NTHR) {
            int cl = t / J;
            float mx = sm.bn[cl * J];
            #pragma unroll
            for (int q = 1; q < J; q++) mx = fmaxf(mx, sm.bn[cl * J + q]);
            float su = 0.f;
            #pragma unroll
            for (int q = 0; q < J; q++) su += expf(sm.bn[cl * J + q] - mx);
            sm.ccs[t] = expf(sm.bn[t] - mx) / su;
        }
        // loop's post-wait __syncthreads orders ccs before first rescale read
    }

    ull acc[5][4];
    #pragma unroll
    for (int jj = 0; jj < 5; jj++)
        #pragma unroll
        for (int t = 0; t < 4; t++) acc[jj][t] = 0ull;

    for (int sc = 0; sc < NSUB; sc++) {
        if (sc > 0) __syncthreads();
        if (sc + 1 < NSUB) {
            issue_W(sm.Wp[(sc + 1) & 1], c0 + (sc + 1) * CCB, tid);
            issue_x(sm.xf[(sc + 1) & 1], c0 + (sc + 1) * CCB, b0, tid);
            cpcommit();
        }
        if (sc + 1 < NSUB) cpwait<1>(); else cpwait<0>();
        __syncthreads();
        ull* Wb = sm.Wp[sc & 1];
        const float* xb = sm.xf[sc & 1];

        if (MODE == 1) {
            const float* cs = sm.ccs + sc * CCB * J;
            #pragma unroll
            for (int t = tid; t < CCB * J * 64; t += NTHR) {
                int row = t >> 6;
                float cv = cs[row];
                ull w = Wb[row * WJS + (t & 63)];
                Wb[row * WJS + (t & 63)] = pack2(lo2(w) * cv, hi2(w) * cv);
            }
            __syncthreads();
        }

        #pragma unroll
        for (int cll = 0; cll < 4; cll++) {
            int cl = ch * 4 + cll;
            const float* xrow = xb + (cl * BT + bq * 4) * IU;
            #pragma unroll
            for (int ih = 0; ih < 2; ih++) {
                ull xd_[4][4];
                #pragma unroll
                for (int t = 0; t < 4; t++) {
                    float4 xf4 = *(const float4*)(xrow + t * IU + ih * 4);
                    xd_[t][0] = dup2(xf4.x);
                    xd_[t][1] = dup2(xf4.y);
                    xd_[t][2] = dup2(xf4.z);
                    xd_[t][3] = dup2(xf4.w);
                }
                const ull* wb_ = Wb + (cl * J + jb) * WJS + ih * 32 + sh;
                #pragma unroll
                for (int jj = 0; jj < 5; jj++) {
                    const ull* w = wb_ + jj * WJS;
                    ull w0 = w[0], w1 = w[8], w2 = w[16], w3 = w[24];
                    #pragma unroll
                    for (int t = 0; t < 4; t++) {
                        fma2(acc[jj][t], w0, xd_[t][0]);
                        fma2(acc[jj][t], w1, xd_[t][1]);
                        fma2(acc[jj][t], w2, xd_[t][2]);
                        fma2(acc[jj][t], w3, xd_[t][3]);
                    }
                }
            }
        }
    }

    // combine c-halves: ch=1 passes acc to ch=0 partner through SMEM
    int t4 = tid & 255;
    #pragma unroll
    for (int jj = 0; jj < 5; jj++) {
        if (ch) {
            sm.ex[t4][0] = acc[jj][0]; sm.ex[t4][1] = acc[jj][1];
            sm.ex[t4][2] = acc[jj][2]; sm.ex[t4][3] = acc[jj][3];
        }
        __syncthreads();
        if (!ch) {
            acc[jj][0] = add2(acc[jj][0], sm.ex[t4][0]);
            acc[jj][1] = add2(acc[jj][1], sm.ex[t4][1]);
            acc[jj][2] = add2(acc[jj][2], sm.ex[t4][2]);
            acc[jj][3] = add2(acc[jj][3], sm.ex[t4][3]);
        }
        __syncthreads();
    }
    if (!ch) {
        ull* spb = g_sp2[cg];
        #pragma unroll
        for (int jj = 0; jj < 5; jj++)
            #pragma unroll
            for (int t = 0; t < 4; t++)
                spb[((size_t)(jb + jj) * B + b0 + bq * 4 + t) * 8 + sh] = acc[jj][t];
    }
}

// ---------------------------------------------------------------------------
// K_b: partial delta_b[c,j] = sum_{b in tile, s} v * u_hat. Raw W (no cc).
// Same ch split; per-warp dsm covers the warp's 4 cl's; W double-buffered.
// ---------------------------------------------------------------------------
__global__ void __launch_bounds__(NTHR, 1) k_b() {
    extern __shared__ char smraw[];
    SMemB& sm = *(SMemB*)smraw;
    int tid = threadIdx.x;
    int cg = blockIdx.x, bt = blockIdx.y;
    int c0 = cg * CG, b0 = bt * BT;
    int sh = tid & 7;
    int jb = ((tid >> 3) & 1) * 5;
    int bq = (tid >> 4) & 15;
    int ch = tid >> 8;
    int warp = tid >> 5, lane = tid & 31;

    gdc_launch();
    issue_W(sm.Wp[0], c0, tid);
    issue_x(sm.xf[0], c0, b0, tid);
    cpcommit();

    gdc_wait();                     // g_v2 written by the preceding k_rs
    ull vv[5][4];
    #pragma unroll
    for (int jj = 0; jj < 5; jj++)
        #pragma unroll
        for (int t = 0; t < 4; t++)
            vv[jj][t] = g_v2[((size_t)(jb + jj) * B + b0 + bq * 4 + t) * 8 + sh];

    for (int sc = 0; sc < NSUB; sc++) {
        if (sc > 0) __syncthreads();         // dsm consumed; buffers reusable
        if (sc + 1 < NSUB) {
            issue_W(sm.Wp[(sc + 1) & 1], c0 + (sc + 1) * CCB, tid);
            issue_x(sm.xf[(sc + 1) & 1], c0 + (sc + 1) * CCB, b0, tid);
            cpcommit();
        }
        if (sc + 1 < NSUB) cpwait<1>(); else cpwait<0>();
        __syncthreads();
        const ull* Wb = sm.Wp[sc & 1];
        const float* xb = sm.xf[sc & 1];

        #pragma unroll 1
        for (int cll = 0; cll < 4; cll++) {
            int cl = ch * 4 + cll;
            ull p2[5] = {0, 0, 0, 0, 0};
            const float* xrow = xb + (cl * BT + bq * 4) * IU;
            ull xd_[4][8];
            #pragma unroll
            for (int t = 0; t < 4; t++) {
                float4 xa = *(const float4*)(xrow + t * IU);
                float4 xc = *(const float4*)(xrow + t * IU + 4);
                xd_[t][0] = dup2(xa.x); xd_[t][1] = dup2(xa.y);
                xd_[t][2] = dup2(xa.z); xd_[t][3] = dup2(xa.w);
                xd_[t][4] = dup2(xc.x); xd_[t][5] = dup2(xc.y);
                xd_[t][6] = dup2(xc.z); xd_[t][7] = dup2(xc.w);
            }
            const ull* wb_ = Wb + (cl * J + jb) * WJS + sh;
            #pragma unroll
            for (int jj = 0; jj < 5; jj++) {
                const ull* w = wb_ + jj * WJS;
                ull w0 = w[0],  w1 = w[8],  w2 = w[16], w3 = w[24];
                ull w4 = w[32], w5 = w[40], w6 = w[48], w7 = w[56];
                #pragma unroll
                for (int t = 0; t < 4; t++) {
                    ull u;
                    asm("mul.rn.f32x2 %0, %1, %2;" : "=l"(u) : "l"(w0), "l"(xd_[t][0]));
                    fma2(u, w1, xd_[t][1]);
                    fma2(u, w2, xd_[t][2]);
                    fma2(u, w3, xd_[t][3]);
                    fma2(u, w4, xd_[t][4]);
                    fma2(u, w5, xd_[t][5]);
                    fma2(u, w6, xd_[t][6]);
                    fma2(u, w7, xd_[t][7]);
                    fma2(p2[jj], vv[jj][t], u);
                }
            }
            #pragma unroll
            for (int jj = 0; jj < 5; jj++) {
                float p = lo2(p2[jj]) + hi2(p2[jj]);
                p += __shfl_xor_sync(0xffffffffu, p, 1);
                p += __shfl_xor_sync(0xffffffffu, p, 2);
                p += __shfl_xor_sync(0xffffffffu, p, 4);
                p += __shfl_xor_sync(0xffffffffu, p, 16);
                if ((lane & 23) == 0)   // lanes 0 (jg0) and 8 (jg1)
                    sm.dsm[warp][cll * J + jb + jj] = p;
            }
        }
        __syncthreads();
        if (tid < CCB * J) {        // 80 outputs per subchunk
            int cl = tid / J, j = tid % J;
            int chh = cl >> 2, cll = cl & 3;
            float s = 0.f;
            #pragma unroll
            for (int w = 0; w < 8; w++) s += sm.dsm[chh * 8 + w][cll * J + j];
            g_bp[bt][(c0 + sc * CCB + cl) * J + j] = s;
        }
    }
}

// ---------------------------------------------------------------------------
// Reduction + squash: 18 partial groups, split 9/9 across thread halves.
// ---------------------------------------------------------------------------
__global__ void __launch_bounds__(512) k_rs(float postscale, float* __restrict__ out) {
    __shared__ ull sh2[256];
    gdc_launch();
    gdc_wait();
    int half = threadIdx.x >> 8;           // 0 or 1
    int t    = threadIdx.x & 255;
    int idx  = blockIdx.x * 256 + t;       // [0, 40960)
    int p0   = half * (NCG / 2);           // 9 each

    ull a0 = g_sp2[p0][idx];
    ull a1 = g_sp2[p0 + 1][idx];
    ull a2 = g_sp2[p0 + 2][idx];
    ull a3 = g_sp2[p0 + 3][idx];
    a0 = add2(a0, g_sp2[p0 + 4][idx]);
    a1 = add2(a1, g_sp2[p0 + 5][idx]);
    a2 = add2(a2, g_sp2[p0 + 6][idx]);
    a3 = add2(a3, g_sp2[p0 + 7][idx]);
    a0 = add2(a0, g_sp2[p0 + 8][idx]);
    ull a = add2(add2(a0, a1), add2(a2, a3));

    if (half) sh2[t] = a;
    __syncthreads();
    if (half) return;
    a = add2(a, sh2[t]);

    float lo = lo2(a) * postscale;
    float hi = hi2(a) * postscale;
    float m = lo * lo + hi * hi;
    m += __shfl_xor_sync(0xffffffffu, m, 1);
    m += __shfl_xor_sync(0xffffffffu, m, 2);
    m += __shfl_xor_sync(0xffffffffu, m, 4);
    float fac = sqrtf(m) / (1.f + m);
    float vlo = lo * fac, vhi = hi * fac;
    g_v2[idx] = pack2(vlo, vhi);
    if (out) {
        int sh = idx & 7;
        int b  = (idx >> 3) & (B - 1);
        int j  = idx >> 12;
        out[(b * J + j) * S + sh]     = vlo;
        out[(b * J + j) * S + sh + 8] = vhi;
    }
}

// ---------------------------------------------------------------------------
// PDL launch helper (degrades to normal serialization if unsupported).
// ---------------------------------------------------------------------------
template <typename K, typename... Args>
static void launch_pdl(K kernel, dim3 g, dim3 b, size_t smem, Args... args) {
    cudaLaunchConfig_t cfg = {};
    cfg.gridDim = g;
    cfg.blockDim = b;
    cfg.dynamicSmemBytes = smem;
    cfg.stream = 0;
    cudaLaunchAttribute attr[1];
    attr[0].id = cudaLaunchAttributeProgrammaticStreamSerialization;
    attr[0].val.programmaticStreamSerializationAllowed = 1;
    cfg.attrs = attr;
    cfg.numAttrs = 1;
    cudaLaunchKernelEx(&cfg, kernel, args...);
}

// ---------------------------------------------------------------------------
extern "C" void kernel_launch(void* const* d_in, const int* in_sizes, int n_in,
                              void* d_out, int out_size) {
    const float* x = (const float*)d_in[0];   // [512][8][1152]
    const float* W = (const float*)d_in[1];   // [1152][10][16][8]
    float* out = (float*)d_out;               // [512][10][16]

    cudaFuncSetAttribute(k_s<0,0>, cudaFuncAttributeMaxDynamicSharedMemorySize,
                         (int)sizeof(SMemS));
    cudaFuncSetAttribute(k_s<1,0>, cudaFuncAttributeMaxDynamicSharedMemorySize,
                         (int)sizeof(SMemS));
    cudaFuncSetAttribute(k_s<1,1>, cudaFuncAttributeMaxDynamicSharedMemorySize,
                         (int)sizeof(SMemS));
    cudaFuncSetAttribute(k_b, cudaFuncAttributeMaxDynamicSharedMemorySize,
                         (int)sizeof(SMemB));

    k_transpose<<<dim3(C / 32, R / 32), dim3(32, 8)>>>(x);
    k_prepW<<<(C * J * WROW + 255) / 256, 256>>>(W);

    dim3 grid(NCG, NBT);              // (18, 8) = 144 blocks
    dim3 blk(NTHR, 1, 1);
    dim3 rgrid(160, 1, 1);
    dim3 rblk(512, 1, 1);

    // t = 0: uniform cc = 1/J folded as postscale
    launch_pdl(k_s<0,0>, grid, blk, sizeof(SMemS));
    launch_pdl(k_rs, rgrid, rblk, 0, 0.1f, (float*)nullptr);

    // t = 1
    launch_pdl(k_b, grid, blk, sizeof(SMemB));
    launch_pdl(k_s<1,0>, grid, blk, sizeof(SMemS));
    launch_pdl(k_rs, rgrid, rblk, 0, 1.f, (float*)nullptr);

    // t = 2
    launch_pdl(k_b, grid, blk, sizeof(SMemB));
    launch_pdl(k_s<1,1>, grid, blk, sizeof(SMemS));
    launch_pdl(k_rs, rgrid, rblk, 0, 1.f, out);
}